// round 1
// baseline (speedup 1.0000x reference)
#include <cuda_runtime.h>
#include <cuda_bf16.h>

#define B 512
#define D 768
#define MARGIN 1.0f

// Scratch (allocation-free rule: __device__ globals)
__device__ float g_dist[B * B];
__device__ float g_sqn[B];
__device__ double g_sum;
__device__ unsigned long long g_count;

__global__ void init_kernel() {
    g_sum = 0.0;
    g_count = 0ull;
}

// One block per row: sum of squares of embedding row.
__global__ void sqnorm_kernel(const float* __restrict__ X) {
    int i = blockIdx.x;
    const float* row = X + (size_t)i * D;
    float acc = 0.f;
    for (int t = threadIdx.x; t < D; t += blockDim.x) {
        float v = row[t];
        acc += v * v;
    }
    #pragma unroll
    for (int o = 16; o; o >>= 1) acc += __shfl_down_sync(0xffffffffu, acc, o);
    __shared__ float ws[8];
    int lane = threadIdx.x & 31, wid = threadIdx.x >> 5;
    if (lane == 0) ws[wid] = acc;
    __syncthreads();
    if (threadIdx.x == 0) {
        float s = 0.f;
        int nw = blockDim.x >> 5;
        for (int w = 0; w < nw; w++) s += ws[w];
        g_sqn[i] = s;
    }
}

// Tiled fp32 Gram + distance epilogue. 32x32 block tile, 16x16 threads,
// 2x2 register micro-tile per thread. K=768 in chunks of 32.
__global__ void dist_kernel(const float* __restrict__ X) {
    __shared__ float As[32][33];
    __shared__ float Bs[32][33];
    int tx = threadIdx.x, ty = threadIdx.y;
    int tid = ty * 16 + tx;
    int rowBase = blockIdx.y * 32;
    int colBase = blockIdx.x * 32;

    float acc00 = 0.f, acc01 = 0.f, acc10 = 0.f, acc11 = 0.f;

    for (int k0 = 0; k0 < D; k0 += 32) {
        #pragma unroll
        for (int i = 0; i < 4; i++) {
            int li = tid + i * 256;
            int r = li >> 5, k = li & 31;
            As[r][k] = X[(size_t)(rowBase + r) * D + k0 + k];
            Bs[r][k] = X[(size_t)(colBase + r) * D + k0 + k];
        }
        __syncthreads();
        #pragma unroll
        for (int k = 0; k < 32; k++) {
            float a0 = As[ty][k],      a1 = As[ty + 16][k];
            float b0 = Bs[tx][k],      b1 = Bs[tx + 16][k];
            acc00 += a0 * b0;
            acc01 += a0 * b1;
            acc10 += a1 * b0;
            acc11 += a1 * b1;
        }
        __syncthreads();
    }

    int r0 = rowBase + ty, r1 = r0 + 16;
    int c0 = colBase + tx, c1 = c0 + 16;
    float sr0 = g_sqn[r0], sr1 = g_sqn[r1];
    float sc0 = g_sqn[c0], sc1 = g_sqn[c1];
    g_dist[r0 * B + c0] = sqrtf(fmaxf(sr0 + sc0 - 2.f * acc00, 0.f));
    g_dist[r0 * B + c1] = sqrtf(fmaxf(sr0 + sc1 - 2.f * acc01, 0.f));
    g_dist[r1 * B + c0] = sqrtf(fmaxf(sr1 + sc0 - 2.f * acc10, 0.f));
    g_dist[r1 * B + c1] = sqrtf(fmaxf(sr1 + sc1 - 2.f * acc11, 0.f));
}

// One block per anchor a: compact dist row into pos/neg lists by type,
// then hinge-sum over the npos x nneg cross product.
__global__ void triplet_kernel(const int* __restrict__ types) {
    int a = blockIdx.x;
    __shared__ float posv[B];
    __shared__ float negv[B];
    __shared__ int cnt[2];
    int tid = threadIdx.x;
    if (tid < 2) cnt[tid] = 0;
    __syncthreads();

    int ta = types[a];
    const float* drow = g_dist + (size_t)a * B;
    for (int j = tid; j < B; j += blockDim.x) {
        float dv = drow[j];
        if (types[j] == ta) {
            int p = atomicAdd(&cnt[0], 1);
            posv[p] = dv;
        } else {
            int p = atomicAdd(&cnt[1], 1);
            negv[p] = dv;
        }
    }
    __syncthreads();

    int np = cnt[0], nn = cnt[1];
    long long total = (long long)np * nn;
    float acc = 0.f;
    for (long long t = tid; t < total; t += blockDim.x) {
        int p = (int)(t / nn);
        int n = (int)(t - (long long)p * nn);
        acc += fmaxf(posv[p] - negv[n] + MARGIN, 0.f);
    }

    #pragma unroll
    for (int o = 16; o; o >>= 1) acc += __shfl_down_sync(0xffffffffu, acc, o);
    __shared__ float ws[8];
    int lane = tid & 31, wid = tid >> 5;
    if (lane == 0) ws[wid] = acc;
    __syncthreads();
    if (tid == 0) {
        float s = 0.f;
        for (int w = 0; w < 8; w++) s += ws[w];
        atomicAdd(&g_sum, (double)s);
        atomicAdd(&g_count, (unsigned long long)total);
    }
}

__global__ void finalize_kernel(float* __restrict__ out) {
    double V = (double)g_count;
    double b3 = 134217728.0;  // 512^3
    // invalid triplets each contribute exactly MARGIN after the clamp
    out[0] = (float)(((b3 - V) * (double)MARGIN + g_sum) / V);
}

extern "C" void kernel_launch(void* const* d_in, const int* in_sizes, int n_in,
                              void* d_out, int out_size) {
    // Expected order: entity_types (512 ints), embeddings (512*768 floats).
    // Be defensive about ordering via element counts.
    int ti = 0, ei = 1;
    if (in_sizes[0] == B * D) { ti = 1; ei = 0; }
    const int* types = (const int*)d_in[ti];
    const float* X = (const float*)d_in[ei];
    float* out = (float*)d_out;

    init_kernel<<<1, 1>>>();
    sqnorm_kernel<<<B, 256>>>(X);
    dim3 grid(B / 32, B / 32), block(16, 16);
    dist_kernel<<<grid, block>>>(X);
    triplet_kernel<<<B, 256>>>(types);
    finalize_kernel<<<1, 1>>>(out);
}

// round 2
// speedup vs baseline: 1.9851x; 1.9851x over previous
#include <cuda_runtime.h>
#include <cuda_bf16.h>

#define B 512
#define D 768
#define MARGIN 1.0f

// Scratch (allocation-free rule: __device__ globals)
__device__ float g_dist[B * B];
__device__ float g_sqn[B];
__device__ double g_sum;
__device__ unsigned long long g_count;

__global__ void init_kernel() {
    g_sum = 0.0;
    g_count = 0ull;
}

// One block per row: sum of squares via float4 loads. 192 threads = 192 float4.
__global__ void sqnorm_kernel(const float* __restrict__ X) {
    int i = blockIdx.x;
    const float4* row = (const float4*)(X + (size_t)i * D);
    float4 v = row[threadIdx.x];
    float acc = v.x * v.x + v.y * v.y + v.z * v.z + v.w * v.w;
    #pragma unroll
    for (int o = 16; o; o >>= 1) acc += __shfl_down_sync(0xffffffffu, acc, o);
    __shared__ float ws[6];
    int lane = threadIdx.x & 31, wid = threadIdx.x >> 5;
    if (lane == 0) ws[wid] = acc;
    __syncthreads();
    if (threadIdx.x == 0) {
        float s = 0.f;
        #pragma unroll
        for (int w = 0; w < 6; w++) s += ws[w];
        g_sqn[i] = s;
    }
}

// Upper-triangle tiled fp32 Gram + distance epilogue.
// 32x32 tiles, 16x16 threads, 2x2 micro-tile. 136 blocks (bx >= by).
// Writes both [r,c] and [c,r]; diagonal forced to exact 0.
__global__ void dist_kernel(const float* __restrict__ X) {
    // linear block index -> upper-triangular (by, bx) over a 16x16 tile grid
    int idx = blockIdx.x, by = 0;
    for (;;) {
        int rowLen = 16 - by;
        if (idx < rowLen) break;
        idx -= rowLen;
        by++;
    }
    int bx = by + idx;

    __shared__ float As[32][33];
    __shared__ float Bs[32][33];
    int tx = threadIdx.x, ty = threadIdx.y;
    int tid = ty * 16 + tx;
    int rowBase = by * 32;
    int colBase = bx * 32;

    // each thread loads one float4 per tile per matrix
    int lr = tid >> 3;          // 0..31 row within tile
    int lq = (tid & 7) * 4;     // 0,4,...,28 col group

    float acc00 = 0.f, acc01 = 0.f, acc10 = 0.f, acc11 = 0.f;

    for (int k0 = 0; k0 < D; k0 += 32) {
        float4 av = *(const float4*)(X + (size_t)(rowBase + lr) * D + k0 + lq);
        float4 bv = *(const float4*)(X + (size_t)(colBase + lr) * D + k0 + lq);
        As[lr][lq + 0] = av.x; As[lr][lq + 1] = av.y;
        As[lr][lq + 2] = av.z; As[lr][lq + 3] = av.w;
        Bs[lr][lq + 0] = bv.x; Bs[lr][lq + 1] = bv.y;
        Bs[lr][lq + 2] = bv.z; Bs[lr][lq + 3] = bv.w;
        __syncthreads();
        #pragma unroll
        for (int k = 0; k < 32; k++) {
            float a0 = As[ty][k],      a1 = As[ty + 16][k];
            float b0 = Bs[tx][k],      b1 = Bs[tx + 16][k];
            acc00 += a0 * b0;
            acc01 += a0 * b1;
            acc10 += a1 * b0;
            acc11 += a1 * b1;
        }
        __syncthreads();
    }

    int r0 = rowBase + ty, r1 = r0 + 16;
    int c0 = colBase + tx, c1 = c0 + 16;
    float sr0 = g_sqn[r0], sr1 = g_sqn[r1];
    float sc0 = g_sqn[c0], sc1 = g_sqn[c1];
    float d00 = (r0 == c0) ? 0.f : sqrtf(fmaxf(sr0 + sc0 - 2.f * acc00, 0.f));
    float d01 = (r0 == c1) ? 0.f : sqrtf(fmaxf(sr0 + sc1 - 2.f * acc01, 0.f));
    float d10 = (r1 == c0) ? 0.f : sqrtf(fmaxf(sr1 + sc0 - 2.f * acc10, 0.f));
    float d11 = (r1 == c1) ? 0.f : sqrtf(fmaxf(sr1 + sc1 - 2.f * acc11, 0.f));
    g_dist[r0 * B + c0] = d00;
    g_dist[r0 * B + c1] = d01;
    g_dist[r1 * B + c0] = d10;
    g_dist[r1 * B + c1] = d11;
    // mirror (diag-block duplicates are harmless, same values)
    g_dist[c0 * B + r0] = d00;
    g_dist[c1 * B + r0] = d01;
    g_dist[c0 * B + r1] = d10;
    g_dist[c1 * B + r1] = d11;
}

// One block per anchor: ballot-compacted pos/neg lists, then
// warp-per-positive x lane-per-negative hinge sum. No divisions.
__global__ void triplet_kernel(const int* __restrict__ types) {
    int a = blockIdx.x;
    __shared__ float posv[B];
    __shared__ float negv[B];
    __shared__ int cnt[2];
    int tid = threadIdx.x;
    int lane = tid & 31, warp = tid >> 5;
    if (tid < 2) cnt[tid] = 0;
    __syncthreads();

    int ta = types[a];
    const float* drow = g_dist + (size_t)a * B;
    unsigned lt_mask = (1u << lane) - 1u;
    #pragma unroll
    for (int j0 = 0; j0 < B; j0 += 256) {
        int j = j0 + tid;
        float dv = drow[j];
        bool isPos = (types[j] == ta);
        unsigned mp = __ballot_sync(0xffffffffu, isPos);
        int cp = __popc(mp);
        int bp = 0, bn = 0;
        if (lane == 0) {
            bp = atomicAdd(&cnt[0], cp);
            bn = atomicAdd(&cnt[1], 32 - cp);
        }
        bp = __shfl_sync(0xffffffffu, bp, 0);
        bn = __shfl_sync(0xffffffffu, bn, 0);
        if (isPos) posv[bp + __popc(mp & lt_mask)] = dv;
        else       negv[bn + __popc((~mp) & lt_mask)] = dv;
    }
    __syncthreads();

    int np = cnt[0], nn = cnt[1];
    float acc = 0.f;
    for (int p = warp; p < np; p += 8) {
        float dp = posv[p] + MARGIN;
        for (int n = lane; n < nn; n += 32)
            acc += fmaxf(dp - negv[n], 0.f);
    }

    #pragma unroll
    for (int o = 16; o; o >>= 1) acc += __shfl_down_sync(0xffffffffu, acc, o);
    __shared__ float ws[8];
    if (lane == 0) ws[warp] = acc;
    __syncthreads();
    if (tid == 0) {
        float s = 0.f;
        #pragma unroll
        for (int w = 0; w < 8; w++) s += ws[w];
        atomicAdd(&g_sum, (double)s);
        atomicAdd(&g_count, (unsigned long long)((long long)np * nn));
    }
}

__global__ void finalize_kernel(float* __restrict__ out) {
    double V = (double)g_count;
    double b3 = 134217728.0;  // 512^3
    out[0] = (float)(((b3 - V) * (double)MARGIN + g_sum) / V);
}

extern "C" void kernel_launch(void* const* d_in, const int* in_sizes, int n_in,
                              void* d_out, int out_size) {
    int ti = 0, ei = 1;
    if (in_sizes[0] == B * D) { ti = 1; ei = 0; }
    const int* types = (const int*)d_in[ti];
    const float* X = (const float*)d_in[ei];
    float* out = (float*)d_out;

    init_kernel<<<1, 1>>>();
    sqnorm_kernel<<<B, 192>>>(X);
    dist_kernel<<<136, dim3(16, 16)>>>(X);
    triplet_kernel<<<B, 256>>>(types);
    finalize_kernel<<<1, 1>>>(out);
}

// round 3
// speedup vs baseline: 2.3573x; 1.1875x over previous
#include <cuda_runtime.h>
#include <cuda_bf16.h>

#define B 512
#define D 768
#define MARGIN 1.0f

// Scratch (allocation-free rule: __device__ globals)
__device__ float g_gram[B * B];   // upper-triangle Gram (dot products), atomically accumulated
__device__ float g_sqn[B];
__device__ double g_sum;
__device__ unsigned long long g_count;

// One block per row: sum of squares via float4. Also zeroes all accumulators
// (stream order guarantees visibility to later kernels in the graph).
__global__ void sqnorm_zero_kernel(const float* __restrict__ X) {
    // zero g_gram: 65536 float4 across 512*192 threads (one store each)
    int gtid = blockIdx.x * blockDim.x + threadIdx.x;
    if (gtid < (B * B) / 4) ((float4*)g_gram)[gtid] = make_float4(0.f, 0.f, 0.f, 0.f);
    if (gtid == 0) { g_sum = 0.0; g_count = 0ull; }

    int i = blockIdx.x;
    const float4* row = (const float4*)(X + (size_t)i * D);
    float4 v = row[threadIdx.x];
    float acc = v.x * v.x + v.y * v.y + v.z * v.z + v.w * v.w;
    #pragma unroll
    for (int o = 16; o; o >>= 1) acc += __shfl_down_sync(0xffffffffu, acc, o);
    __shared__ float ws[6];
    int lane = threadIdx.x & 31, wid = threadIdx.x >> 5;
    if (lane == 0) ws[wid] = acc;
    __syncthreads();
    if (threadIdx.x == 0) {
        float s = 0.f;
        #pragma unroll
        for (int w = 0; w < 6; w++) s += ws[w];
        g_sqn[i] = s;
    }
}

// Upper-triangle Gram: 64x64 tiles, 16x16 threads, 4x4 micro-tile,
// K-split x4 (192 per block) accumulated with atomicAdd.
// grid = (36 triangle tiles, 4 k-slices)
__global__ void gram_kernel(const float* __restrict__ X) {
    // linear tile index -> (by, bx) with bx >= by over 8x8 tile grid
    int idx = blockIdx.x, by = 0;
    for (;;) {
        int len = 8 - by;
        if (idx < len) break;
        idx -= len;
        by++;
    }
    int bx = by + idx;
    int rowBase = by * 64;
    int colBase = bx * 64;
    int k0 = blockIdx.y * 192;

    __shared__ float As[16][68];  // [k][row], padded; k-rows stay 16B aligned (68*4=272)
    __shared__ float Bs[16][68];

    int tx = threadIdx.x, ty = threadIdx.y;
    int tid = ty * 16 + tx;
    int lr = tid & 63;   // row/col within tile for the global load
    int lq = tid >> 6;   // 0..3 -> k-quad

    float acc[4][4];
    #pragma unroll
    for (int i = 0; i < 4; i++)
        #pragma unroll
        for (int j = 0; j < 4; j++) acc[i][j] = 0.f;

    for (int kc = 0; kc < 192; kc += 16) {
        int kk = k0 + kc + lq * 4;
        float4 av = *(const float4*)(X + (size_t)(rowBase + lr) * D + kk);
        float4 bv = *(const float4*)(X + (size_t)(colBase + lr) * D + kk);
        As[lq * 4 + 0][lr] = av.x; As[lq * 4 + 1][lr] = av.y;
        As[lq * 4 + 2][lr] = av.z; As[lq * 4 + 3][lr] = av.w;
        Bs[lq * 4 + 0][lr] = bv.x; Bs[lq * 4 + 1][lr] = bv.y;
        Bs[lq * 4 + 2][lr] = bv.z; Bs[lq * 4 + 3][lr] = bv.w;
        __syncthreads();
        #pragma unroll
        for (int k = 0; k < 16; k++) {
            float4 a4 = *(const float4*)&As[k][ty * 4];
            float4 b4 = *(const float4*)&Bs[k][tx * 4];
            float a[4] = {a4.x, a4.y, a4.z, a4.w};
            float b[4] = {b4.x, b4.y, b4.z, b4.w};
            #pragma unroll
            for (int i = 0; i < 4; i++)
                #pragma unroll
                for (int j = 0; j < 4; j++) acc[i][j] += a[i] * b[j];
        }
        __syncthreads();
    }

    #pragma unroll
    for (int i = 0; i < 4; i++) {
        int r = rowBase + ty * 4 + i;
        #pragma unroll
        for (int j = 0; j < 4; j++) {
            int c = colBase + tx * 4 + j;
            atomicAdd(&g_gram[r * B + c], acc[i][j]);
        }
    }
}

// One block per anchor: compute distances from gram+sqn on the fly,
// ballot-compact pos/neg lists, then warp-per-positive hinge sum with
// float4 negv reads (padded with +INF so extras contribute 0).
__global__ void triplet_kernel(const int* __restrict__ types) {
    int a = blockIdx.x;
    __shared__ float posv[B];
    __shared__ __align__(16) float negv[B + 4];
    __shared__ int cnt[2];
    int tid = threadIdx.x;
    int lane = tid & 31, warp = tid >> 5;
    if (tid < 2) cnt[tid] = 0;
    __syncthreads();

    int ta = types[a];
    float sa = g_sqn[a];
    unsigned lt_mask = (1u << lane) - 1u;
    #pragma unroll
    for (int j0 = 0; j0 < B; j0 += 256) {
        int j = j0 + tid;
        float g = (j >= a) ? g_gram[a * B + j] : g_gram[j * B + a];
        float dv = (j == a) ? 0.f
                            : sqrtf(fmaxf(sa + g_sqn[j] - 2.f * g, 0.f));
        bool isPos = (types[j] == ta);
        unsigned mp = __ballot_sync(0xffffffffu, isPos);
        int cp = __popc(mp);
        int bp = 0, bn = 0;
        if (lane == 0) {
            bp = atomicAdd(&cnt[0], cp);
            bn = atomicAdd(&cnt[1], 32 - cp);
        }
        bp = __shfl_sync(0xffffffffu, bp, 0);
        bn = __shfl_sync(0xffffffffu, bn, 0);
        if (isPos) posv[bp + __popc(mp & lt_mask)] = dv;
        else       negv[bn + __popc((~mp) & lt_mask)] = dv;
    }
    __syncthreads();

    int np = cnt[0], nn = cnt[1];
    int nn4 = (nn + 3) & ~3;
    if (tid < nn4 - nn) negv[nn + tid] = 1e30f;  // pad: max(dp - INF, 0) = 0
    __syncthreads();

    const float4* negv4 = (const float4*)negv;
    int nq = nn4 >> 2;
    float acc = 0.f;
    for (int p = warp; p < np; p += 8) {
        float dp = posv[p] + MARGIN;
        for (int n = lane; n < nq; n += 32) {
            float4 v = negv4[n];
            acc += fmaxf(dp - v.x, 0.f);
            acc += fmaxf(dp - v.y, 0.f);
            acc += fmaxf(dp - v.z, 0.f);
            acc += fmaxf(dp - v.w, 0.f);
        }
    }

    #pragma unroll
    for (int o = 16; o; o >>= 1) acc += __shfl_down_sync(0xffffffffu, acc, o);
    __shared__ float ws[8];
    if (lane == 0) ws[warp] = acc;
    __syncthreads();
    if (tid == 0) {
        float s = 0.f;
        #pragma unroll
        for (int w = 0; w < 8; w++) s += ws[w];
        atomicAdd(&g_sum, (double)s);
        atomicAdd(&g_count, (unsigned long long)((long long)np * nn));
    }
}

__global__ void finalize_kernel(float* __restrict__ out) {
    double V = (double)g_count;
    double b3 = 134217728.0;  // 512^3
    out[0] = (float)(((b3 - V) * (double)MARGIN + g_sum) / V);
}

extern "C" void kernel_launch(void* const* d_in, const int* in_sizes, int n_in,
                              void* d_out, int out_size) {
    int ti = 0, ei = 1;
    if (in_sizes[0] == B * D) { ti = 1; ei = 0; }
    const int* types = (const int*)d_in[ti];
    const float* X = (const float*)d_in[ei];
    float* out = (float*)d_out;

    sqnorm_zero_kernel<<<B, 192>>>(X);
    gram_kernel<<<dim3(36, 4), dim3(16, 16)>>>(X);
    triplet_kernel<<<B, 256>>>(types);
    finalize_kernel<<<1, 1>>>(out);
}